// round 4
// baseline (speedup 1.0000x reference)
#include <cuda_runtime.h>
#include <cstdint>

// C = triu(A @ B), A,B upper-triangular fp32, N=4096.
// Round 4: TF32 mma.sync GEMM, occupancy 2 CTAs/SM + split-K load balancing.
//   - 128x128 output tiles; tiles with K-length > 1024 split into even pieces.
//   - Split pieces accumulate via red.global.add.f32 into memset-zeroed C.
//   - Schedule table (1000 pieces, longest diagonals first) copied H2D async.
//   - 3-stage cp.async pipeline (107.5KB smem) so 2 CTAs co-reside per SM.

#define N_DIM 4096
#define BM 128
#define BN 128
#define BK 32
#define STAGES 3
#define NTHREADS 256
#define SPLIT_L 8     // max K-chunks (of 128) per CTA before splitting

#define AP 36    // A smem row pitch (floats): conflict-free fragment loads
#define BP 136   // B smem row pitch (floats): conflict-free fragment loads
#define A_STAGE_FL (BM * AP)
#define B_STAGE_FL (BK * BP)
#define B_BASE_FL  (STAGES * A_STAGE_FL)
#define SMEM_FL    (B_BASE_FL + STAGES * B_STAGE_FL)   // 26880 fl = 107520 B

#define MAX_PIECES 1024
__device__ int4 g_sched[MAX_PIECES];

__device__ __forceinline__ uint32_t smem_u32(const void* p) {
    uint32_t a;
    asm("{ .reg .u64 t; cvta.to.shared.u64 t, %1; cvt.u32.u64 %0, t; }" : "=r"(a) : "l"(p));
    return a;
}
__device__ __forceinline__ void cp_async16(uint32_t dst, const float* src) {
    asm volatile("cp.async.cg.shared.global [%0], [%1], 16;" :: "r"(dst), "l"(src));
}
__device__ __forceinline__ uint32_t ld_tf32(const float* p) {
    uint32_t r;
    float v = *p;
    asm("cvt.rna.tf32.f32 %0, %1;" : "=r"(r) : "f"(v));
    return r;
}
__device__ __forceinline__ void red_add_f32(float* p, float v) {
    asm volatile("red.global.add.f32 [%0], %1;" :: "l"(p), "f"(v) : "memory");
}

__global__ __launch_bounds__(NTHREADS, 2)
void triu_gemm_tf32mma_kernel(const float* __restrict__ A,
                              const float* __restrict__ B,
                              float* __restrict__ C)
{
    extern __shared__ float sm[];
    const uint32_t smb = smem_u32(sm);

    const int tid  = threadIdx.x;
    const int wid  = tid >> 5;
    const int lane = tid & 31;
    const int qrow = lane >> 2;   // 0..7
    const int qcol = lane & 3;    // 0..3

    const int4 e  = g_sched[blockIdx.x];
    const int it    = e.x;
    const int jt    = e.y;
    const int k_beg = e.z;
    const int k_end = e.w;
    const int nch   = (k_end - k_beg) / BK;
    const bool split = (jt - it + 1) > SPLIT_L;

    const int row0 = it * BM;
    const int col0 = jt * BN;

    // Warp tile: 64(m) x 32(n); warps 2(m) x 4(n).
    const int wm = (wid & 1) * 64;
    const int wn = (wid >> 1) * 32;

    float acc[4][4][4];
#pragma unroll
    for (int i = 0; i < 4; i++)
#pragma unroll
        for (int j = 0; j < 4; j++)
#pragma unroll
            for (int r = 0; r < 4; r++) acc[i][j][r] = 0.0f;

    // cp.async thread mapping
    const int arow = tid >> 3;   // A: row base 0..31 (+32 per rep), 8 segs/row
    const int aseg = tid & 7;
    const int brow = tid >> 5;   // B: k-row base 0..7 (+8 per rep), 32 segs/row
    const int bseg = tid & 31;

    const float* Ag = A + (size_t)(row0 + arow) * N_DIM + aseg * 4;
    const float* Bg = B + (size_t)brow * N_DIM + col0 + bseg * 4;

#define LOAD_STAGE(s, kc)                                                        \
    do {                                                                         \
        const uint32_t abase = smb + ((s) * A_STAGE_FL) * 4;                     \
        const uint32_t bbase = smb + (B_BASE_FL + (s) * B_STAGE_FL) * 4;         \
        _Pragma("unroll")                                                        \
        for (int r = 0; r < 4; r++)                                             \
            cp_async16(abase + ((arow + r * 32) * AP + aseg * 4) * 4,            \
                       Ag + (size_t)(r * 32) * N_DIM + (kc));                    \
        _Pragma("unroll")                                                        \
        for (int r = 0; r < 4; r++)                                             \
            cp_async16(bbase + ((brow + r * 8) * BP + bseg * 4) * 4,             \
                       Bg + (size_t)((kc) + r * 8) * N_DIM);                     \
    } while (0)

#pragma unroll
    for (int s = 0; s < STAGES - 1; s++) {
        LOAD_STAGE(s, k_beg + s * BK);
        asm volatile("cp.async.commit_group;" ::: "memory");
    }

    for (int i = 0; i < nch; i++) {
        asm volatile("cp.async.wait_group %0;" :: "n"(STAGES - 2) : "memory");
        __syncthreads();

        if (i + STAGES - 1 < nch) {
            int s = i + STAGES - 1;
            while (s >= STAGES) s -= STAGES;
            LOAD_STAGE(s, k_beg + (i + STAGES - 1) * BK);
        }
        asm volatile("cp.async.commit_group;" ::: "memory");

        int s = i;
        while (s >= STAGES) s -= STAGES;
        s = i % STAGES;
        const float* As = sm + s * A_STAGE_FL;
        const float* Bs = sm + B_BASE_FL + s * B_STAGE_FL;

#pragma unroll
        for (int ks = 0; ks < BK / 8; ks++) {
            const int k0 = ks * 8;
            uint32_t af[4][4], bf[4][2];
#pragma unroll
            for (int mt = 0; mt < 4; mt++) {
                const float* ap = As + (wm + mt * 16 + qrow) * AP + k0 + qcol;
                af[mt][0] = ld_tf32(ap);
                af[mt][1] = ld_tf32(ap + 8 * AP);
                af[mt][2] = ld_tf32(ap + 4);
                af[mt][3] = ld_tf32(ap + 8 * AP + 4);
            }
#pragma unroll
            for (int nt = 0; nt < 4; nt++) {
                const float* bp = Bs + (k0 + qcol) * BP + wn + nt * 8 + qrow;
                bf[nt][0] = ld_tf32(bp);
                bf[nt][1] = ld_tf32(bp + 4 * BP);
            }
#pragma unroll
            for (int mt = 0; mt < 4; mt++)
#pragma unroll
                for (int nt = 0; nt < 4; nt++) {
                    asm volatile(
                        "mma.sync.aligned.m16n8k8.row.col.f32.tf32.tf32.f32 "
                        "{%0,%1,%2,%3}, {%4,%5,%6,%7}, {%8,%9}, {%0,%1,%2,%3};"
                        : "+f"(acc[mt][nt][0]), "+f"(acc[mt][nt][1]),
                          "+f"(acc[mt][nt][2]), "+f"(acc[mt][nt][3])
                        : "r"(af[mt][0]), "r"(af[mt][1]),
                          "r"(af[mt][2]), "r"(af[mt][3]),
                          "r"(bf[nt][0]), "r"(bf[nt][1]));
                }
        }
        __syncthreads();
    }

    // ---- Epilogue ----
    if (split) {
        // Split tiles are strictly above the diagonal: plain atomic accumulate.
#pragma unroll
        for (int mt = 0; mt < 4; mt++) {
            const int r_lo = row0 + wm + mt * 16 + qrow;
            float* crow_lo = C + (size_t)r_lo * N_DIM;
            float* crow_hi = crow_lo + (size_t)8 * N_DIM;
#pragma unroll
            for (int nt = 0; nt < 4; nt++) {
                const int gc = col0 + wn + nt * 8 + qcol * 2;
                red_add_f32(crow_lo + gc,     acc[mt][nt][0]);
                red_add_f32(crow_lo + gc + 1, acc[mt][nt][1]);
                red_add_f32(crow_hi + gc,     acc[mt][nt][2]);
                red_add_f32(crow_hi + gc + 1, acc[mt][nt][3]);
            }
        }
    } else {
#pragma unroll
        for (int mt = 0; mt < 4; mt++) {
            const int r_lo = row0 + wm + mt * 16 + qrow;
            const int r_hi = r_lo + 8;
            float* crow_lo = C + (size_t)r_lo * N_DIM;
            float* crow_hi = C + (size_t)r_hi * N_DIM;
#pragma unroll
            for (int nt = 0; nt < 4; nt++) {
                const int gc = col0 + wn + nt * 8 + qcol * 2;
                float2 v0, v1;
                v0.x = (gc + 0 >= r_lo) ? acc[mt][nt][0] : 0.0f;
                v0.y = (gc + 1 >= r_lo) ? acc[mt][nt][1] : 0.0f;
                v1.x = (gc + 0 >= r_hi) ? acc[mt][nt][2] : 0.0f;
                v1.y = (gc + 1 >= r_hi) ? acc[mt][nt][3] : 0.0f;
                *reinterpret_cast<float2*>(crow_lo + gc) = v0;
                *reinterpret_cast<float2*>(crow_hi + gc) = v1;
            }
        }
    }
}

extern "C" void kernel_launch(void* const* d_in, const int* in_sizes, int n_in,
                              void* d_out, int out_size) {
    const float* A = (const float*)d_in[0];
    const float* B = (const float*)d_in[1];
    float* C = (float*)d_out;

    // Build schedule: longest diagonals first; tiles with more than SPLIT_L
    // 128-chunks of K are split into even pieces (accumulated atomically).
    static int4 h_sched[MAX_PIECES];
    int cnt = 0;
    for (int d = 31; d >= 0; d--) {
        const int len = d + 1;                          // K-chunks of 128
        const int pieces = (len + SPLIT_L - 1) / SPLIT_L;
        for (int it = 0; it + d < 32; it++) {
            const int jt = it + d;
            for (int q = 0; q < pieces; q++) {
                const int c0 = it + (q * len) / pieces;
                const int c1 = it + ((q + 1) * len) / pieces;
                h_sched[cnt].x = it;
                h_sched[cnt].y = jt;
                h_sched[cnt].z = c0 * BM;
                h_sched[cnt].w = c1 * BM;
                cnt++;
            }
        }
    }

    cudaFuncSetAttribute(triu_gemm_tf32mma_kernel,
                         cudaFuncAttributeMaxDynamicSharedMemorySize,
                         SMEM_FL * sizeof(float));

    cudaMemcpyToSymbolAsync(g_sched, h_sched, cnt * sizeof(int4), 0,
                            cudaMemcpyHostToDevice, 0);
    cudaMemsetAsync(d_out, 0, (size_t)N_DIM * N_DIM * sizeof(float), 0);
    triu_gemm_tf32mma_kernel<<<cnt, NTHREADS, SMEM_FL * sizeof(float)>>>(A, B, C);
}